// round 7
// baseline (speedup 1.0000x reference)
#include <cuda_runtime.h>
#include <cuda_bf16.h>
#include <mma.h>
#include <cstdint>

using namespace nvcuda;

#define KPOLY 3
#define NN 10000
#define SPLITS 12           // 3 polys x 4 K-quarters
#define KSPL 2560           // K per split (last: 2320); 64-aligned boundaries
#define KCH 32
#define MTILE 128
#define MT ((NN + MTILE - 1) / MTILE)  // 79

// ---------------- scratch (static device arrays; no allocation) ----------------
__device__ __align__(16) unsigned short g_T1h[(size_t)64 * KPOLY * NN];
__device__ __align__(16) unsigned short g_T1l[(size_t)64 * KPOLY * NN];
__device__ __align__(16) unsigned short g_T2h[(size_t)32 * KPOLY * NN];
__device__ __align__(16) unsigned short g_T2l[(size_t)32 * KPOLY * NN];
__device__ float g_P1[(size_t)SPLITS * NN * 64];
__device__ float g_P2[(size_t)SPLITS * NN * 32];

__device__ __forceinline__ uint32_t smem_u32(const void* p) {
    uint32_t a;
    asm("{ .reg .u64 t; cvta.to.shared.u64 t, %1; cvt.u32.u64 %0, t; }" : "=r"(a) : "l"(p));
    return a;
}
__device__ __forceinline__ uint32_t prmt7632(uint32_t a, uint32_t b) {
    uint32_t r;
    asm("prmt.b32 %0, %1, %2, 0x7632;" : "=r"(r) : "r"(a), "r"(b));
    return r;
}
__device__ __forceinline__ uint32_t pkbf(float a, float b) {  // a -> low 16 bits (RNE)
    uint32_t r;
    asm("cvt.rn.bf16x2.f32 %0, %1, %2;" : "=r"(r) : "f"(b), "f"(a));
    return r;
}

#define CP_ASYNC(dst, src, pb) \
    asm volatile("cp.async.cg.shared.global [%0], [%1], 16, %2;" \
        :: "r"(dst), "l"(src), "r"(pb) : "memory")
#define CP_COMMIT() asm volatile("cp.async.commit_group;" ::: "memory")
#define CP_WAIT1()  asm volatile("cp.async.wait_group 1;" ::: "memory")

// =======================================================================
// poly MMA kernel: P[split] = poly_slice @ T_slice.
// A: fp32 poly via cp.async -> per-warp trunc-split (hi=trunc16, lo=RNE
//    bf16 of residual) into warp-private single-buffered bf16 planes.
// B: pre-split T planes via cp.async (from gemm_xw).
// 3-stage pipeline, KCH=32, pass-major 3-MMA split accumulation.
// =======================================================================
template <int C>
__global__ void __launch_bounds__(256, 2)
poly_mma_kernel(const float* __restrict__ poly,
                const unsigned short* __restrict__ Bhg,
                const unsigned short* __restrict__ Blg,
                float* __restrict__ P) {
    constexpr int LDAF = 36;                 // fp32 stage pitch (floats); <=2-way LDS conflicts
    constexpr int ABYTF = MTILE * LDAF * 4;  // 18432
    constexpr int LDB = 40;
    constexpr int BBYT = C * LDB * 2;
    constexpr int SS = ABYTF + 2 * BBYT;     // stage size
    constexpr int LDA = 32;                  // converted bf16 pitch (elements)
    constexpr int CVT_OFF = 3 * SS;          // converted planes: Ah then Al (8KB each)
    constexpr int CVTP = MTILE * LDA * 2;    // 8192 per plane
    constexpr int NT = C / 16;
    extern __shared__ __align__(128) char smem[];
    const uint32_t sb = smem_u32(smem);

    const int tid = threadIdx.x;
    const int warp = tid >> 5;
    const int lane = tid & 31;
    const int split = blockIdx.y;
    const int k = split >> 2;
    const int mbase = (split & 3) * KSPL;
    const int klen = min(NN - mbase, KSPL);
    const int nch = (klen + KCH - 1) / KCH;
    const int row0 = blockIdx.x * MTILE;

    // ---- B cp.async addressing (plane C x 32 per chunk; 16B per lane) ----
    const int bc = tid >> 2, bk8 = (tid & 3) * 8;
    const unsigned short* bsrcH = Bhg + ((size_t)bc * KPOLY + k) * NN + mbase + bk8;
    const unsigned short* bsrcL = Blg + ((size_t)bc * KPOLY + k) * NN + mbase + bk8;
    const uint32_t bdoff = (uint32_t)(ABYTF + (bc * LDB + bk8) * 2);
    auto issueB = [&](int ch) {
        if (C == 64 || tid < 128) {
            const int mc = ch * KCH;
            const int kv = klen - mc;
            const int pb = (bk8 < kv) ? 16 : 0;
            const unsigned short* sh = pb ? (bsrcH + mc) : bsrcH;
            const unsigned short* sl = pb ? (bsrcL + mc) : bsrcL;
            const uint32_t d = sb + (ch % 3) * SS + bdoff;
            CP_ASYNC(d, sh, pb);
            CP_ASYNC(d + BBYT, sl, pb);
        }
    };

    // ---- A fp32 cp.async: thread t covers row t>>1, 16 cols at (t&1)*16 ----
    const int ar = tid >> 1;
    const int ac0 = (tid & 1) * 16;
    const int arow = min(row0 + ar, NN - 1);  // clamp; those rows discarded at store
    const float* asrc = poly + (size_t)k * NN * NN + (size_t)arow * NN + mbase + ac0;
    const uint32_t adoff = (uint32_t)((ar * LDAF + ac0) * 4);
    auto issueA = [&](int ch) {
        const int mc = ch * KCH;
        const int kv = klen - mc;  // multiple of 16 on every real chunk
        const int pb = (ac0 < kv) ? 16 : 0;
        const float* s = pb ? (asrc + mc) : asrc;
        const uint32_t d = sb + (ch % 3) * SS + adoff;
#pragma unroll
        for (int j = 0; j < 4; j++) CP_ASYNC(d + j * 16, s + j * 4, pb);
    };

    // ---- per-warp convert: fp32 stage -> warp-private bf16 hi/lo planes ----
    const int crow = warp * 16 + (lane >> 1);   // this lane's row
    const int cc0 = (lane & 1) * 16;            // this lane's 16-col half
    auto convertA = [&](int ch) {
        const float* As = (const float*)(smem + (ch % 3) * SS) + crow * LDAF + cc0;
        char* Ah = smem + CVT_OFF;
        char* Al = Ah + CVTP;
        uint32_t h[8], l[8];
#pragma unroll
        for (int j = 0; j < 4; j++) {
            float4 v = *(const float4*)(As + j * 4);
            uint32_t ux = __float_as_uint(v.x), uy = __float_as_uint(v.y);
            uint32_t uz = __float_as_uint(v.z), uw = __float_as_uint(v.w);
            h[2 * j]     = prmt7632(ux, uy);
            h[2 * j + 1] = prmt7632(uz, uw);
            float lx = v.x - __uint_as_float(ux & 0xFFFF0000u);
            float ly = v.y - __uint_as_float(uy & 0xFFFF0000u);
            float lz = v.z - __uint_as_float(uz & 0xFFFF0000u);
            float lw = v.w - __uint_as_float(uw & 0xFFFF0000u);
            l[2 * j]     = pkbf(lx, ly);
            l[2 * j + 1] = pkbf(lz, lw);
        }
        const uint32_t o = (uint32_t)((crow * LDA + cc0) * 2);
        *(uint4*)(Ah + o)      = make_uint4(h[0], h[1], h[2], h[3]);
        *(uint4*)(Ah + o + 16) = make_uint4(h[4], h[5], h[6], h[7]);
        *(uint4*)(Al + o)      = make_uint4(l[0], l[1], l[2], l[3]);
        *(uint4*)(Al + o + 16) = make_uint4(l[4], l[5], l[6], l[7]);
        __syncwarp();
    };

    // ---- accumulators & MMA ----
    wmma::fragment<wmma::accumulator, 16, 16, 16, float> acc[NT];
#pragma unroll
    for (int n = 0; n < NT; n++) wmma::fill_fragment(acc[n], 0.0f);

    auto domma = [&](int ch) {
        const __nv_bfloat16* Ahp = (const __nv_bfloat16*)(smem + CVT_OFF);
        const __nv_bfloat16* Alp = Ahp + MTILE * LDA;
        const __nv_bfloat16* Bhp = (const __nv_bfloat16*)(smem + (ch % 3) * SS + ABYTF);
        const __nv_bfloat16* Blp = Bhp + C * LDB;
#pragma unroll
        for (int ks = 0; ks < 2; ks++) {
            wmma::fragment<wmma::matrix_a, 16, 16, 16, __nv_bfloat16, wmma::row_major> fah, fal;
            wmma::load_matrix_sync(fah, Ahp + warp * 16 * LDA + ks * 16, LDA);
            wmma::load_matrix_sync(fal, Alp + warp * 16 * LDA + ks * 16, LDA);
            wmma::fragment<wmma::matrix_b, 16, 16, 16, __nv_bfloat16, wmma::col_major> fbh[NT];
#pragma unroll
            for (int n = 0; n < NT; n++)
                wmma::load_matrix_sync(fbh[n], Bhp + n * 16 * LDB + ks * 16, LDB);
#pragma unroll
            for (int n = 0; n < NT; n++) wmma::mma_sync(acc[n], fah, fbh[n], acc[n]);
            {
                wmma::fragment<wmma::matrix_b, 16, 16, 16, __nv_bfloat16, wmma::col_major> fbl;
#pragma unroll
                for (int n = 0; n < NT; n++) {
                    wmma::load_matrix_sync(fbl, Blp + n * 16 * LDB + ks * 16, LDB);
                    wmma::mma_sync(acc[n], fah, fbl, acc[n]);
                }
            }
#pragma unroll
            for (int n = 0; n < NT; n++) wmma::mma_sync(acc[n], fal, fbh[n], acc[n]);
        }
    };

    // ---- pipeline ----
    issueA(0); issueB(0); CP_COMMIT();
    issueA(1); issueB(1); CP_COMMIT();

    for (int ch = 0; ch < nch; ch++) {
        CP_WAIT1();
        __syncthreads();     // stage (ch+2)%3 == (ch-1)%3 free: all warps past domma(ch-1)
        issueA(ch + 2); issueB(ch + 2); CP_COMMIT();
        convertA(ch);        // warp-local; cvt buffer reuse is warp-sequential
        domma(ch);
    }

    // ---- store partials (warp tile fully valid or invalid: 10000-9984=16) ----
    const int nrow = row0 + warp * 16;
    if (nrow < NN) {
        float* o = P + ((size_t)split * NN + nrow) * C;
#pragma unroll
        for (int n = 0; n < NT; n++)
            wmma::store_matrix_sync(o + n * 16, acc[n], C, wmma::mem_row_major);
    }
}

// =======================================================================
// Small GEMM: Tt[c][k][n] = (X @ W[k])[n][c] split into bf16 hi/lo (RNE).
// RED: X := relu(sum_s P1[s]) read on the fly.
// =======================================================================
template <int DOUT, bool RED>
__global__ void __launch_bounds__(256)
gemm_xw_kernel(const float* __restrict__ X, const float* __restrict__ W,
               unsigned short* __restrict__ Th, unsigned short* __restrict__ Tl) {
    constexpr int DIN = 64;
    constexpr int MR = 256 / (DOUT / 8);
    __shared__ float Ws[DIN * DOUT];
    __shared__ float Xs[MR * (DIN + 1)];
    const int tid = threadIdx.x;
    const int kb = blockIdx.y;
    const int m0 = blockIdx.x * MR;

    for (int i = tid; i < DIN * DOUT; i += 256)
        Ws[i] = W[(size_t)kb * DIN * DOUT + i];
    for (int i = tid; i < MR * DIN; i += 256) {
        int r = i >> 6, d = i & 63;
        int n = m0 + r;
        if (n > NN - 1) n = NN - 1;
        float v;
        if (!RED) {
            v = X[(size_t)n * DIN + d];
        } else {
            v = 0.f;
#pragma unroll
            for (int s = 0; s < SPLITS; s++) v += g_P1[((size_t)s * NN + n) * 64 + d];
            v = fmaxf(v, 0.f);
        }
        Xs[r * (DIN + 1) + d] = v;
    }
    __syncthreads();

    const int row = tid % MR;
    const int c0 = (tid / MR) * 8;
    float a[8];
#pragma unroll
    for (int c = 0; c < 8; c++) a[c] = 0.f;
#pragma unroll
    for (int d = 0; d < DIN; d++) {
        float xv = Xs[row * (DIN + 1) + d];
        float4 wa = *(const float4*)&Ws[d * DOUT + c0];
        float4 wb = *(const float4*)&Ws[d * DOUT + c0 + 4];
        a[0] = fmaf(xv, wa.x, a[0]); a[1] = fmaf(xv, wa.y, a[1]);
        a[2] = fmaf(xv, wa.z, a[2]); a[3] = fmaf(xv, wa.w, a[3]);
        a[4] = fmaf(xv, wb.x, a[4]); a[5] = fmaf(xv, wb.y, a[5]);
        a[6] = fmaf(xv, wb.z, a[6]); a[7] = fmaf(xv, wb.w, a[7]);
    }
    const int n = m0 + row;
    if (n < NN) {
#pragma unroll
        for (int c = 0; c < 8; c++) {
            float v = a[c];
            uint32_t u = __float_as_uint(v);
            uint32_t r = (u + 0x7FFFu + ((u >> 16) & 1u)) & 0xFFFF0000u;
            float lof = v - __uint_as_float(r);
            unsigned short ls;
            asm("cvt.rn.bf16.f32 %0, %1;" : "=h"(ls) : "f"(lof));
            size_t idx = ((size_t)(c0 + c) * KPOLY + kb) * NN + n;
            Th[idx] = (unsigned short)(r >> 16);
            Tl[idx] = ls;
        }
    }
}

// Final reduction of layer-1 partials into d_out
__global__ void reduce_out_kernel(float* __restrict__ out) {
    int i = blockIdx.x * blockDim.x + threadIdx.x;
    if (i < NN * 32 / 4) {
        float4 acc = make_float4(0.f, 0.f, 0.f, 0.f);
#pragma unroll
        for (int s = 0; s < SPLITS; s++) {
            float4 v = *(const float4*)(g_P2 + (size_t)s * NN * 32 + (size_t)i * 4);
            acc.x += v.x; acc.y += v.y; acc.z += v.z; acc.w += v.w;
        }
        *(float4*)(out + (size_t)i * 4) = acc;
    }
}

extern "C" void kernel_launch(void* const* d_in, const int* in_sizes, int n_in,
                              void* d_out, int out_size) {
    const float* x    = (const float*)d_in[0];
    const float* poly = (const float*)d_in[1];
    const float* W1   = (const float*)d_in[2];
    const float* W2   = (const float*)d_in[3];
    float* out = (float*)d_out;

    // smem: 3 stages (fp32 A + B planes) + 16KB convert buffers
    constexpr int SS64 = 128 * 36 * 4 + 2 * (64 * 40 * 2);  // 28672
    constexpr int SS32 = 128 * 36 * 4 + 2 * (32 * 40 * 2);  // 23552
    constexpr int SMEM64 = 3 * SS64 + 2 * (128 * 32 * 2);   // 102400
    constexpr int SMEM32 = 3 * SS32 + 2 * (128 * 32 * 2);   // 87040
    cudaFuncSetAttribute((const void*)poly_mma_kernel<64>,
                         cudaFuncAttributeMaxDynamicSharedMemorySize, SMEM64);
    cudaFuncSetAttribute((const void*)poly_mma_kernel<32>,
                         cudaFuncAttributeMaxDynamicSharedMemorySize, SMEM32);

    unsigned short *T1h, *T1l, *T2h, *T2l;
    float *P1, *P2;
    cudaGetSymbolAddress((void**)&T1h, g_T1h);
    cudaGetSymbolAddress((void**)&T1l, g_T1l);
    cudaGetSymbolAddress((void**)&T2h, g_T2h);
    cudaGetSymbolAddress((void**)&T2l, g_T2l);
    cudaGetSymbolAddress((void**)&P1, g_P1);
    cudaGetSymbolAddress((void**)&P2, g_P2);

    dim3 g1((NN + 31) / 32, KPOLY);
    dim3 g2((NN + 63) / 64, KPOLY);
    dim3 gp(MT, SPLITS);

    gemm_xw_kernel<64, false><<<g1, 256>>>(x, W1, T1h, T1l);      // T1^T hi/lo
    poly_mma_kernel<64><<<gp, 256, SMEM64>>>(poly, T1h, T1l, P1); // P1 = poly @ T1
    gemm_xw_kernel<32, true><<<g2, 256>>>(x, W2, T2h, T2l);       // T2^T = relu(sum P1) @ W2
    poly_mma_kernel<32><<<gp, 256, SMEM32>>>(poly, T2h, T2l, P2); // P2 = poly @ T2
    reduce_out_kernel<<<(NN * 32 / 4 + 255) / 256, 256>>>(out);
}

// round 8
// speedup vs baseline: 1.1609x; 1.1609x over previous
#include <cuda_runtime.h>
#include <cuda_bf16.h>
#include <mma.h>
#include <cstdint>

using namespace nvcuda;

#define KPOLY 3
#define NN 10000
#define SPLITS 12           // 3 polys x 4 K-quarters
#define KSPL 2560           // K per split (last: 2320); 64-aligned boundaries
#define KCH 32
#define MTILE 256
#define MTG ((NN + MTILE - 1) / MTILE)  // 40
#define TOTE ((size_t)KPOLY * NN * NN)

// ---------------- scratch (static device arrays; no allocation) ----------------
__device__ __align__(16) unsigned short g_T1h[(size_t)64 * KPOLY * NN];
__device__ __align__(16) unsigned short g_T1l[(size_t)64 * KPOLY * NN];
__device__ __align__(16) unsigned short g_T2h[(size_t)32 * KPOLY * NN];
__device__ __align__(16) unsigned short g_T2l[(size_t)32 * KPOLY * NN];
__device__ __align__(16) unsigned short g_Ah[TOTE];  // presplit poly hi (trunc16)
__device__ __align__(16) unsigned short g_Al[TOTE];  // presplit poly lo
__device__ float g_P1[(size_t)SPLITS * NN * 64];
__device__ float g_P2[(size_t)SPLITS * NN * 32];

__device__ __forceinline__ uint32_t smem_u32(const void* p) {
    uint32_t a;
    asm("{ .reg .u64 t; cvta.to.shared.u64 t, %1; cvt.u32.u64 %0, t; }" : "=r"(a) : "l"(p));
    return a;
}
__device__ __forceinline__ uint32_t prmt7632(uint32_t a, uint32_t b) {
    uint32_t r;
    asm("prmt.b32 %0, %1, %2, 0x7632;" : "=r"(r) : "r"(a), "r"(b));
    return r;
}
__device__ __forceinline__ uint32_t pkbf(float a, float b) {  // a -> low 16 bits (RNE)
    uint32_t r;
    asm("cvt.rn.bf16x2.f32 %0, %1, %2;" : "=r"(r) : "f"(b), "f"(a));
    return r;
}

#define CP_ASYNC(dst, src, pb) \
    asm volatile("cp.async.cg.shared.global [%0], [%1], 16, %2;" \
        :: "r"(dst), "l"(src), "r"(pb) : "memory")
#define CP_COMMIT() asm volatile("cp.async.commit_group;" ::: "memory")
#define CP_WAIT1()  asm volatile("cp.async.wait_group 1;" ::: "memory")

// =======================================================================
// presplit: poly fp32 -> (hi, lo) bf16 planes (proven round 6).
// =======================================================================
__global__ void __launch_bounds__(256)
presplit_kernel(const float* __restrict__ poly,
                unsigned short* __restrict__ Ah,
                unsigned short* __restrict__ Al) {
    const size_t base = ((size_t)blockIdx.x * 256 + threadIdx.x) * 16;
    if (base >= TOTE) return;
    const float4* src = (const float4*)(poly + base);
    uint32_t h[8], l[8];
#pragma unroll
    for (int j = 0; j < 4; j++) {
        float4 v = src[j];
        uint32_t ux = __float_as_uint(v.x), uy = __float_as_uint(v.y);
        uint32_t uz = __float_as_uint(v.z), uw = __float_as_uint(v.w);
        h[2 * j]     = prmt7632(ux, uy);
        h[2 * j + 1] = prmt7632(uz, uw);
        float lx = v.x - __uint_as_float(ux & 0xFFFF0000u);
        float ly = v.y - __uint_as_float(uy & 0xFFFF0000u);
        float lz = v.z - __uint_as_float(uz & 0xFFFF0000u);
        float lw = v.w - __uint_as_float(uw & 0xFFFF0000u);
        l[2 * j]     = pkbf(lx, ly);
        l[2 * j + 1] = pkbf(lz, lw);
    }
    uint4* dh = (uint4*)(Ah + base);
    uint4* dl = (uint4*)(Al + base);
    dh[0] = make_uint4(h[0], h[1], h[2], h[3]);
    dh[1] = make_uint4(h[4], h[5], h[6], h[7]);
    dl[0] = make_uint4(l[0], l[1], l[2], l[3]);
    dl[1] = make_uint4(l[4], l[5], l[6], l[7]);
}

// =======================================================================
// poly MMA kernel (PRE planes): MTILE=256, 8 warps x 32 rows (2 row-frags),
// KCH=32, STG-stage cp.async pipeline (3 for C=32, 2 for C=64).
// =======================================================================
template <int C, int STG>
__global__ void __launch_bounds__(256, 2)
poly_mma_kernel(const unsigned short* __restrict__ Bhg,
                const unsigned short* __restrict__ Blg,
                const unsigned short* __restrict__ Ahg,
                const unsigned short* __restrict__ Alg,
                float* __restrict__ P) {
    constexpr int LDA = 32, LDB = 40;
    constexpr int APL = MTILE * LDA * 2;   // 16384 per A plane per stage
    constexpr int BPL = C * LDB * 2;       // 5120 / 2560
    constexpr int SS = 2 * APL + 2 * BPL;
    constexpr int NT = C / 16;
    extern __shared__ __align__(128) char smem[];
    const uint32_t sb = smem_u32(smem);

    const int tid = threadIdx.x;
    const int warp = tid >> 5;
    const int split = blockIdx.y;
    const int k = split >> 2;
    const int mbase = (split & 3) * KSPL;
    const int klen = min(NN - mbase, KSPL);
    const int nch = (klen + KCH - 1) / KCH;
    const int row0 = blockIdx.x * MTILE;

    // ---- B cp.async (plane C x 32 per chunk) ----
    const int bc = tid >> 2, bk8 = (tid & 3) * 8;
    const unsigned short* bsrcH = Bhg + ((size_t)bc * KPOLY + k) * NN + mbase + bk8;
    const unsigned short* bsrcL = Blg + ((size_t)bc * KPOLY + k) * NN + mbase + bk8;
    const uint32_t bdoff = (uint32_t)(2 * APL + (bc * LDB + bk8) * 2);
    auto issueB = [&](int ch) {
        if (C == 64 || tid < 128) {
            const int mc = ch * KCH;
            const int kv = klen - mc;
            const int pb = (bk8 < kv) ? 16 : 0;
            const unsigned short* sh = pb ? (bsrcH + mc) : bsrcH;
            const unsigned short* sl = pb ? (bsrcL + mc) : bsrcL;
            const uint32_t d = sb + (ch % STG) * SS + bdoff;
            CP_ASYNC(d, sh, pb);
            CP_ASYNC(d + BPL, sl, pb);
        }
    };

    // ---- A plane cp.async: thread covers rows ar+64j (j=0..3), cols ak8..+7 ----
    const int ar = tid >> 2, ak8 = (tid & 3) * 8;
    const unsigned short* asrcH[4];
    const unsigned short* asrcL[4];
    uint32_t adoff[4];
#pragma unroll
    for (int j = 0; j < 4; j++) {
        const int r = ar + j * 64;
        const int arow = min(row0 + r, NN - 1);  // clamp; rows discarded at store
        asrcH[j] = Ahg + ((size_t)k * NN + arow) * NN + mbase + ak8;
        asrcL[j] = Alg + ((size_t)k * NN + arow) * NN + mbase + ak8;
        adoff[j] = (uint32_t)((r * LDA + ak8) * 2);
    }
    auto issueA = [&](int ch) {
        const int mc = ch * KCH;
        const int kv = klen - mc;
        const int pb = (ak8 < kv) ? 16 : 0;
        const uint32_t base = sb + (ch % STG) * SS;
#pragma unroll
        for (int j = 0; j < 4; j++) {
            const unsigned short* sh = pb ? (asrcH[j] + mc) : asrcH[j];
            const unsigned short* sl = pb ? (asrcL[j] + mc) : asrcL[j];
            CP_ASYNC(base + adoff[j], sh, pb);
            CP_ASYNC(base + APL + adoff[j], sl, pb);
        }
    };

    // ---- accumulators: 2 row-frags x NT ----
    wmma::fragment<wmma::accumulator, 16, 16, 16, float> acc[2][NT];
#pragma unroll
    for (int r = 0; r < 2; r++)
#pragma unroll
        for (int n = 0; n < NT; n++) wmma::fill_fragment(acc[r][n], 0.0f);

    auto domma = [&](int ch) {
        const __nv_bfloat16* Ahp = (const __nv_bfloat16*)(smem + (ch % STG) * SS);
        const __nv_bfloat16* Alp = Ahp + MTILE * LDA;
        const __nv_bfloat16* Bhp = (const __nv_bfloat16*)(smem + (ch % STG) * SS + 2 * APL);
        const __nv_bfloat16* Blp = Bhp + C * LDB;
        const int wr = warp * 32;
#pragma unroll
        for (int ks = 0; ks < 2; ks++) {
            wmma::fragment<wmma::matrix_a, 16, 16, 16, __nv_bfloat16, wmma::row_major> fah[2], fal[2];
#pragma unroll
            for (int r = 0; r < 2; r++) {
                wmma::load_matrix_sync(fah[r], Ahp + (wr + r * 16) * LDA + ks * 16, LDA);
                wmma::load_matrix_sync(fal[r], Alp + (wr + r * 16) * LDA + ks * 16, LDA);
            }
            wmma::fragment<wmma::matrix_b, 16, 16, 16, __nv_bfloat16, wmma::col_major> fbh[NT];
#pragma unroll
            for (int n = 0; n < NT; n++)
                wmma::load_matrix_sync(fbh[n], Bhp + n * 16 * LDB + ks * 16, LDB);
            // pass hi*hi
#pragma unroll
            for (int n = 0; n < NT; n++)
#pragma unroll
                for (int r = 0; r < 2; r++) wmma::mma_sync(acc[r][n], fah[r], fbh[n], acc[r][n]);
            // pass hi*lo (fbl loaded once per n, shared by both row-frags)
            {
                wmma::fragment<wmma::matrix_b, 16, 16, 16, __nv_bfloat16, wmma::col_major> fbl;
#pragma unroll
                for (int n = 0; n < NT; n++) {
                    wmma::load_matrix_sync(fbl, Blp + n * 16 * LDB + ks * 16, LDB);
#pragma unroll
                    for (int r = 0; r < 2; r++) wmma::mma_sync(acc[r][n], fah[r], fbl, acc[r][n]);
                }
            }
            // pass lo*hi
#pragma unroll
            for (int n = 0; n < NT; n++)
#pragma unroll
                for (int r = 0; r < 2; r++) wmma::mma_sync(acc[r][n], fal[r], fbh[n], acc[r][n]);
        }
    };

    // ---- pipeline ----
    if (STG == 3) {
        issueA(0); issueB(0); CP_COMMIT();
        issueA(1); issueB(1); CP_COMMIT();
        for (int ch = 0; ch < nch; ch++) {
            CP_WAIT1();
            __syncthreads();              // group(ch) visible; all past domma(ch-1)
            issueA(ch + 2); issueB(ch + 2); CP_COMMIT();
            domma(ch);
        }
    } else {  // STG == 2: two-barrier handshake
        issueA(0); issueB(0); CP_COMMIT();
        for (int ch = 0; ch < nch; ch++) {
            __syncthreads();              // all warps done domma(ch-1): stage (ch+1)%2 free
            issueA(ch + 1); issueB(ch + 1); CP_COMMIT();
            CP_WAIT1();                   // group(ch) arrived
            __syncthreads();              // visibility
            domma(ch);
        }
    }

    // ---- store partials (16-row frag granularity; NN-9984=16 => frag-exact) ----
#pragma unroll
    for (int r = 0; r < 2; r++) {
        const int nrow = row0 + warp * 32 + r * 16;
        if (nrow < NN) {
            float* o = P + ((size_t)split * NN + nrow) * C;
#pragma unroll
            for (int n = 0; n < NT; n++)
                wmma::store_matrix_sync(o + n * 16, acc[r][n], C, wmma::mem_row_major);
        }
    }
}

// =======================================================================
// Small GEMM: Tt[c][k][n] = (X @ W[k])[n][c] split into bf16 hi/lo (RNE).
// RED: X := relu(sum_s P1[s]) read on the fly.
// =======================================================================
template <int DOUT, bool RED>
__global__ void __launch_bounds__(256)
gemm_xw_kernel(const float* __restrict__ X, const float* __restrict__ W,
               unsigned short* __restrict__ Th, unsigned short* __restrict__ Tl) {
    constexpr int DIN = 64;
    constexpr int MR = 256 / (DOUT / 8);
    __shared__ float Ws[DIN * DOUT];
    __shared__ float Xs[MR * (DIN + 1)];
    const int tid = threadIdx.x;
    const int kb = blockIdx.y;
    const int m0 = blockIdx.x * MR;

    for (int i = tid; i < DIN * DOUT; i += 256)
        Ws[i] = W[(size_t)kb * DIN * DOUT + i];
    for (int i = tid; i < MR * DIN; i += 256) {
        int r = i >> 6, d = i & 63;
        int n = m0 + r;
        if (n > NN - 1) n = NN - 1;
        float v;
        if (!RED) {
            v = X[(size_t)n * DIN + d];
        } else {
            v = 0.f;
#pragma unroll
            for (int s = 0; s < SPLITS; s++) v += g_P1[((size_t)s * NN + n) * 64 + d];
            v = fmaxf(v, 0.f);
        }
        Xs[r * (DIN + 1) + d] = v;
    }
    __syncthreads();

    const int row = tid % MR;
    const int c0 = (tid / MR) * 8;
    float a[8];
#pragma unroll
    for (int c = 0; c < 8; c++) a[c] = 0.f;
#pragma unroll
    for (int d = 0; d < DIN; d++) {
        float xv = Xs[row * (DIN + 1) + d];
        float4 wa = *(const float4*)&Ws[d * DOUT + c0];
        float4 wb = *(const float4*)&Ws[d * DOUT + c0 + 4];
        a[0] = fmaf(xv, wa.x, a[0]); a[1] = fmaf(xv, wa.y, a[1]);
        a[2] = fmaf(xv, wa.z, a[2]); a[3] = fmaf(xv, wa.w, a[3]);
        a[4] = fmaf(xv, wb.x, a[4]); a[5] = fmaf(xv, wb.y, a[5]);
        a[6] = fmaf(xv, wb.z, a[6]); a[7] = fmaf(xv, wb.w, a[7]);
    }
    const int n = m0 + row;
    if (n < NN) {
#pragma unroll
        for (int c = 0; c < 8; c++) {
            float v = a[c];
            uint32_t u = __float_as_uint(v);
            uint32_t r = (u + 0x7FFFu + ((u >> 16) & 1u)) & 0xFFFF0000u;
            float lof = v - __uint_as_float(r);
            unsigned short ls;
            asm("cvt.rn.bf16.f32 %0, %1;" : "=h"(ls) : "f"(lof));
            size_t idx = ((size_t)(c0 + c) * KPOLY + kb) * NN + n;
            Th[idx] = (unsigned short)(r >> 16);
            Tl[idx] = ls;
        }
    }
}

// Final reduction of layer-1 partials into d_out
__global__ void reduce_out_kernel(float* __restrict__ out) {
    int i = blockIdx.x * blockDim.x + threadIdx.x;
    if (i < NN * 32 / 4) {
        float4 acc = make_float4(0.f, 0.f, 0.f, 0.f);
#pragma unroll
        for (int s = 0; s < SPLITS; s++) {
            float4 v = *(const float4*)(g_P2 + (size_t)s * NN * 32 + (size_t)i * 4);
            acc.x += v.x; acc.y += v.y; acc.z += v.z; acc.w += v.w;
        }
        *(float4*)(out + (size_t)i * 4) = acc;
    }
}

extern "C" void kernel_launch(void* const* d_in, const int* in_sizes, int n_in,
                              void* d_out, int out_size) {
    const float* x    = (const float*)d_in[0];
    const float* poly = (const float*)d_in[1];
    const float* W1   = (const float*)d_in[2];
    const float* W2   = (const float*)d_in[3];
    float* out = (float*)d_out;

    constexpr int SS64 = 2 * (MTILE * 32 * 2) + 2 * (64 * 40 * 2);  // 43008
    constexpr int SS32 = 2 * (MTILE * 32 * 2) + 2 * (32 * 40 * 2);  // 37888
    constexpr int SMEM64 = 2 * SS64;  // 86016  (2-stage)
    constexpr int SMEM32 = 3 * SS32;  // 113664 (3-stage)
    cudaFuncSetAttribute((const void*)poly_mma_kernel<64, 2>,
                         cudaFuncAttributeMaxDynamicSharedMemorySize, SMEM64);
    cudaFuncSetAttribute((const void*)poly_mma_kernel<32, 3>,
                         cudaFuncAttributeMaxDynamicSharedMemorySize, SMEM32);

    unsigned short *T1h, *T1l, *T2h, *T2l, *Ah, *Al;
    float *P1, *P2;
    cudaGetSymbolAddress((void**)&T1h, g_T1h);
    cudaGetSymbolAddress((void**)&T1l, g_T1l);
    cudaGetSymbolAddress((void**)&T2h, g_T2h);
    cudaGetSymbolAddress((void**)&T2l, g_T2l);
    cudaGetSymbolAddress((void**)&Ah, g_Ah);
    cudaGetSymbolAddress((void**)&Al, g_Al);
    cudaGetSymbolAddress((void**)&P1, g_P1);
    cudaGetSymbolAddress((void**)&P2, g_P2);

    dim3 g1((NN + 31) / 32, KPOLY);
    dim3 g2((NN + 63) / 64, KPOLY);
    dim3 gp(MTG, SPLITS);
    const int psBlocks = (int)((TOTE / 16 + 255) / 256);

    presplit_kernel<<<psBlocks, 256>>>(poly, Ah, Al);
    gemm_xw_kernel<64, false><<<g1, 256>>>(x, W1, T1h, T1l);
    poly_mma_kernel<64, 2><<<gp, 256, SMEM64>>>(T1h, T1l, Ah, Al, P1);
    gemm_xw_kernel<32, true><<<g2, 256>>>(x, W2, T2h, T2l);
    poly_mma_kernel<32, 3><<<gp, 256, SMEM32>>>(T2h, T2l, Ah, Al, P2);
    reduce_out_kernel<<<(NN * 32 / 4 + 255) / 256, 256>>>(out);
}

// round 9
// speedup vs baseline: 1.4321x; 1.2336x over previous
#include <cuda_runtime.h>
#include <cuda_fp16.h>
#include <mma.h>
#include <cstdint>

using namespace nvcuda;

#define KPOLY 3
#define NN 10000
#define SPLITS 12           // 3 polys x 4 K-quarters
#define KSPL 2560           // K per split (last: 2320); 64-aligned boundaries
#define KCH 32
#define MTILE 256
#define MTG ((NN + MTILE - 1) / MTILE)  // 40
#define TOTE ((size_t)KPOLY * NN * NN)
#define SCALE 8192.0f       // poly pre-scale: keeps fp16 normal
#define INV_SCALE (1.0f / 8192.0f)

// ---------------- scratch (static device arrays; no allocation) ----------------
__device__ __align__(16) half g_T1[(size_t)64 * KPOLY * NN];   // T1^T fp16 [c][k][n]
__device__ __align__(16) half g_T2[(size_t)32 * KPOLY * NN];
__device__ __align__(16) half g_Af[TOTE];                      // poly * SCALE, fp16
__device__ float g_P1[(size_t)SPLITS * NN * 64];
__device__ float g_P2[(size_t)SPLITS * NN * 32];

__device__ __forceinline__ uint32_t smem_u32(const void* p) {
    uint32_t a;
    asm("{ .reg .u64 t; cvta.to.shared.u64 t, %1; cvt.u32.u64 %0, t; }" : "=r"(a) : "l"(p));
    return a;
}

#define CP_ASYNC(dst, src, pb) \
    asm volatile("cp.async.cg.shared.global [%0], [%1], 16, %2;" \
        :: "r"(dst), "l"(src), "r"(pb) : "memory")
#define CP_COMMIT() asm volatile("cp.async.commit_group;" ::: "memory")
#define CP_WAIT1()  asm volatile("cp.async.wait_group 1;" ::: "memory")
#define CP_WAIT2()  asm volatile("cp.async.wait_group 2;" ::: "memory")

// =======================================================================
// presplit: poly fp32 -> fp16 (scaled by SCALE). Pure streaming, 1.8 GB.
// =======================================================================
__global__ void __launch_bounds__(256)
presplit_kernel(const float* __restrict__ poly, half* __restrict__ Af) {
    const size_t base = ((size_t)blockIdx.x * 256 + threadIdx.x) * 16;
    if (base >= TOTE) return;
    const float4* src = (const float4*)(poly + base);
    uint32_t h[8];
#pragma unroll
    for (int j = 0; j < 4; j++) {
        float4 v = src[j];
        __half2 a = __floats2half2_rn(v.x * SCALE, v.y * SCALE);
        __half2 b = __floats2half2_rn(v.z * SCALE, v.w * SCALE);
        h[2 * j]     = *(const uint32_t*)&a;
        h[2 * j + 1] = *(const uint32_t*)&b;
    }
    uint4* d = (uint4*)(Af + base);
    d[0] = make_uint4(h[0], h[1], h[2], h[3]);
    d[1] = make_uint4(h[4], h[5], h[6], h[7]);
}

// =======================================================================
// poly MMA kernel: single-pass fp16. MTILE=256, 8 warps x 32 rows
// (2 row-frags), KCH=32, STG-stage cp.async pipeline.
// LDA=LDB=40 halves (80B row stride: conflict-free ldmatrix, 16B aligned).
// =======================================================================
template <int C, int STG, int NCTA>
__global__ void __launch_bounds__(256, NCTA)
poly_mma_kernel(const half* __restrict__ Bg,
                const half* __restrict__ Ag,
                float* __restrict__ P) {
    constexpr int LDA = 40, LDB = 40;
    constexpr int APL = MTILE * LDA * 2;   // 20480
    constexpr int BPL = C * LDB * 2;       // 5120 / 2560
    constexpr int SS = APL + BPL;
    constexpr int NT = C / 16;
    extern __shared__ __align__(128) char smem[];
    const uint32_t sb = smem_u32(smem);

    const int tid = threadIdx.x;
    const int warp = tid >> 5;
    const int split = blockIdx.y;
    const int k = split >> 2;
    const int mbase = (split & 3) * KSPL;
    const int klen = min(NN - mbase, KSPL);
    const int nch = (klen + KCH - 1) / KCH;
    const int row0 = blockIdx.x * MTILE;

    // ---- B cp.async: plane C x 32 halves per chunk ----
    const int bc = tid >> 2, bk8 = (tid & 3) * 8;
    const half* bsrc = Bg + ((size_t)bc * KPOLY + k) * NN + mbase + bk8;
    const uint32_t bdoff = (uint32_t)(APL + (bc * LDB + bk8) * 2);
    auto issueB = [&](int ch) {
        if (C == 64 || tid < 128) {
            const int mc = ch * KCH;
            const int kv = klen - mc;
            const int pb = (bk8 < kv) ? 16 : 0;
            CP_ASYNC(sb + (ch % STG) * SS + bdoff, pb ? (bsrc + mc) : bsrc, pb);
        }
    };

    // ---- A cp.async: rows ar+64j (j=0..3), cols ak8..+7 ----
    const int ar = tid >> 2, ak8 = (tid & 3) * 8;
    const half* asrc[4];
    uint32_t adoff[4];
#pragma unroll
    for (int j = 0; j < 4; j++) {
        const int r = ar + j * 64;
        const int arow = min(row0 + r, NN - 1);  // clamp; rows discarded at store
        asrc[j] = Ag + ((size_t)k * NN + arow) * NN + mbase + ak8;
        adoff[j] = (uint32_t)((r * LDA + ak8) * 2);
    }
    auto issueA = [&](int ch) {
        const int mc = ch * KCH;
        const int kv = klen - mc;
        const int pb = (ak8 < kv) ? 16 : 0;
        const uint32_t base = sb + (ch % STG) * SS;
#pragma unroll
        for (int j = 0; j < 4; j++)
            CP_ASYNC(base + adoff[j], pb ? (asrc[j] + mc) : asrc[j], pb);
    };

    // ---- accumulators: 2 row-frags x NT ----
    wmma::fragment<wmma::accumulator, 16, 16, 16, float> acc[2][NT];
#pragma unroll
    for (int r = 0; r < 2; r++)
#pragma unroll
        for (int n = 0; n < NT; n++) wmma::fill_fragment(acc[r][n], 0.0f);

    auto domma = [&](int ch) {
        const half* Ap = (const half*)(smem + (ch % STG) * SS);
        const half* Bp = (const half*)(smem + (ch % STG) * SS + APL);
        const int wr = warp * 32;
#pragma unroll
        for (int ks = 0; ks < 2; ks++) {
            wmma::fragment<wmma::matrix_a, 16, 16, 16, half, wmma::row_major> fa[2];
#pragma unroll
            for (int r = 0; r < 2; r++)
                wmma::load_matrix_sync(fa[r], Ap + (wr + r * 16) * LDA + ks * 16, LDA);
#pragma unroll
            for (int n = 0; n < NT; n++) {
                wmma::fragment<wmma::matrix_b, 16, 16, 16, half, wmma::col_major> fb;
                wmma::load_matrix_sync(fb, Bp + n * 16 * LDB + ks * 16, LDB);
                wmma::mma_sync(acc[0][n], fa[0], fb, acc[0][n]);
                wmma::mma_sync(acc[1][n], fa[1], fb, acc[1][n]);
            }
        }
    };

    // ---- pipeline: STG stages, STG-1 groups in flight ----
#pragma unroll
    for (int i = 0; i < STG - 1; i++) { issueA(i); issueB(i); CP_COMMIT(); }
    for (int ch = 0; ch < nch; ch++) {
        if (STG == 4) CP_WAIT2(); else CP_WAIT1();
        __syncthreads();   // group(ch) visible; all warps past domma(ch-1)
        issueA(ch + STG - 1); issueB(ch + STG - 1); CP_COMMIT();
        domma(ch);
    }

    // ---- store partials (16-row frag granularity; NN-9984=16 => frag-exact) ----
#pragma unroll
    for (int r = 0; r < 2; r++) {
        const int nrow = row0 + warp * 32 + r * 16;
        if (nrow < NN) {
            float* o = P + ((size_t)split * NN + nrow) * C;
#pragma unroll
            for (int n = 0; n < NT; n++)
                wmma::store_matrix_sync(o + n * 16, acc[r][n], C, wmma::mem_row_major);
        }
    }
}

// =======================================================================
// Small GEMM: Tt[c][k][n] = (X @ W[k])[n][c] as fp16.
// RED: X := relu(sum_s P1[s]) * INV_SCALE (descale layer-1 output).
// =======================================================================
template <int DOUT, bool RED>
__global__ void __launch_bounds__(256)
gemm_xw_kernel(const float* __restrict__ X, const float* __restrict__ W,
               half* __restrict__ T) {
    constexpr int DIN = 64;
    constexpr int MR = 256 / (DOUT / 8);
    __shared__ float Ws[DIN * DOUT];
    __shared__ float Xs[MR * (DIN + 1)];
    const int tid = threadIdx.x;
    const int kb = blockIdx.y;
    const int m0 = blockIdx.x * MR;

    for (int i = tid; i < DIN * DOUT; i += 256)
        Ws[i] = W[(size_t)kb * DIN * DOUT + i];
    for (int i = tid; i < MR * DIN; i += 256) {
        int r = i >> 6, d = i & 63;
        int n = m0 + r;
        if (n > NN - 1) n = NN - 1;
        float v;
        if (!RED) {
            v = X[(size_t)n * DIN + d];
        } else {
            v = 0.f;
#pragma unroll
            for (int s = 0; s < SPLITS; s++) v += g_P1[((size_t)s * NN + n) * 64 + d];
            v = fmaxf(v, 0.f) * INV_SCALE;   // relu + descale (P1 carries SCALE)
        }
        Xs[r * (DIN + 1) + d] = v;
    }
    __syncthreads();

    const int row = tid % MR;
    const int c0 = (tid / MR) * 8;
    float a[8];
#pragma unroll
    for (int c = 0; c < 8; c++) a[c] = 0.f;
#pragma unroll
    for (int d = 0; d < DIN; d++) {
        float xv = Xs[row * (DIN + 1) + d];
        float4 wa = *(const float4*)&Ws[d * DOUT + c0];
        float4 wb = *(const float4*)&Ws[d * DOUT + c0 + 4];
        a[0] = fmaf(xv, wa.x, a[0]); a[1] = fmaf(xv, wa.y, a[1]);
        a[2] = fmaf(xv, wa.z, a[2]); a[3] = fmaf(xv, wa.w, a[3]);
        a[4] = fmaf(xv, wb.x, a[4]); a[5] = fmaf(xv, wb.y, a[5]);
        a[6] = fmaf(xv, wb.z, a[6]); a[7] = fmaf(xv, wb.w, a[7]);
    }
    const int n = m0 + row;
    if (n < NN) {
#pragma unroll
        for (int c = 0; c < 8; c++)
            T[((size_t)(c0 + c) * KPOLY + kb) * NN + n] = __float2half_rn(a[c]);
    }
}

// Final reduction of layer-1 partials into d_out (descale P2's SCALE factor)
__global__ void reduce_out_kernel(float* __restrict__ out) {
    int i = blockIdx.x * blockDim.x + threadIdx.x;
    if (i < NN * 32 / 4) {
        float4 acc = make_float4(0.f, 0.f, 0.f, 0.f);
#pragma unroll
        for (int s = 0; s < SPLITS; s++) {
            float4 v = *(const float4*)(g_P2 + (size_t)s * NN * 32 + (size_t)i * 4);
            acc.x += v.x; acc.y += v.y; acc.z += v.z; acc.w += v.w;
        }
        acc.x *= INV_SCALE; acc.y *= INV_SCALE; acc.z *= INV_SCALE; acc.w *= INV_SCALE;
        *(float4*)(out + (size_t)i * 4) = acc;
    }
}

extern "C" void kernel_launch(void* const* d_in, const int* in_sizes, int n_in,
                              void* d_out, int out_size) {
    const float* x    = (const float*)d_in[0];
    const float* poly = (const float*)d_in[1];
    const float* W1   = (const float*)d_in[2];
    const float* W2   = (const float*)d_in[3];
    float* out = (float*)d_out;

    constexpr int SS64 = MTILE * 40 * 2 + 64 * 40 * 2;  // 25600
    constexpr int SS32 = MTILE * 40 * 2 + 32 * 40 * 2;  // 23040
    constexpr int SMEM64 = 4 * SS64;  // 102400 (4-stage, 2 CTAs/SM)
    constexpr int SMEM32 = 3 * SS32;  // 69120  (3-stage, 3 CTAs/SM)
    cudaFuncSetAttribute((const void*)poly_mma_kernel<64, 4, 2>,
                         cudaFuncAttributeMaxDynamicSharedMemorySize, SMEM64);
    cudaFuncSetAttribute((const void*)poly_mma_kernel<32, 3, 3>,
                         cudaFuncAttributeMaxDynamicSharedMemorySize, SMEM32);

    half *T1, *T2, *Af;
    float *P1, *P2;
    cudaGetSymbolAddress((void**)&T1, g_T1);
    cudaGetSymbolAddress((void**)&T2, g_T2);
    cudaGetSymbolAddress((void**)&Af, g_Af);
    cudaGetSymbolAddress((void**)&P1, g_P1);
    cudaGetSymbolAddress((void**)&P2, g_P2);

    dim3 g1((NN + 31) / 32, KPOLY);
    dim3 g2((NN + 63) / 64, KPOLY);
    dim3 gp(MTG, SPLITS);
    const int psBlocks = (int)((TOTE / 16 + 255) / 256);

    presplit_kernel<<<psBlocks, 256>>>(poly, Af);                 // poly*S -> fp16
    gemm_xw_kernel<64, false><<<g1, 256>>>(x, W1, T1);            // T1^T fp16
    poly_mma_kernel<64, 4, 2><<<gp, 256, SMEM64>>>(T1, Af, P1);   // P1 = S*poly @ T1
    gemm_xw_kernel<32, true><<<g2, 256>>>(x, W2, T2);             // T2 = relu(sum P1 /S) @ W2
    poly_mma_kernel<32, 3, 3><<<gp, 256, SMEM32>>>(T2, Af, P2);   // P2 = S*poly @ T2
    reduce_out_kernel<<<(NN * 32 / 4 + 255) / 256, 256>>>(out);   // out = sum P2 / S
}

// round 10
// speedup vs baseline: 2.1148x; 1.4767x over previous
#include <cuda_runtime.h>
#include <cuda_fp16.h>
#include <mma.h>
#include <cstdint>

using namespace nvcuda;

#define KPOLY 3
#define NN 10000
#define SPLITS 12           // 3 polys x 4 K-quarters
#define KSPL 2560           // K per split (last: 2320); 64-aligned boundaries
#define KCH 32
#define MTILE 256
#define MTG ((NN + MTILE - 1) / MTILE)  // 40
#define TOTE ((size_t)KPOLY * NN * NN)
#define SCALE 8192.0f       // poly pre-scale: keeps fp16 normal
#define INV_SCALE (1.0f / 8192.0f)

// ---------------- scratch (static device arrays; no allocation) ----------------
__device__ __align__(16) half g_T1[(size_t)64 * KPOLY * NN];   // T1^T fp16 [c][k][n]
__device__ __align__(16) half g_T2[(size_t)32 * KPOLY * NN];
__device__ __align__(16) half g_Af[TOTE];                      // poly * SCALE, fp16
__device__ float g_P1[(size_t)SPLITS * NN * 64];
__device__ float g_P2[(size_t)SPLITS * NN * 32];
__device__ __align__(16) float g_X1[(size_t)NN * 64];          // relu(sum P1)/S

__device__ __forceinline__ uint32_t smem_u32(const void* p) {
    uint32_t a;
    asm("{ .reg .u64 t; cvta.to.shared.u64 t, %1; cvt.u32.u64 %0, t; }" : "=r"(a) : "l"(p));
    return a;
}

#define CP_ASYNC(dst, src, pb) \
    asm volatile("cp.async.cg.shared.global [%0], [%1], 16, %2;" \
        :: "r"(dst), "l"(src), "r"(pb) : "memory")
#define CP_COMMIT() asm volatile("cp.async.commit_group;" ::: "memory")
#define CP_WAIT1()  asm volatile("cp.async.wait_group 1;" ::: "memory")
#define CP_WAIT2()  asm volatile("cp.async.wait_group 2;" ::: "memory")

// =======================================================================
// presplit: poly fp32 -> fp16 (scaled by SCALE). Pure streaming, 1.8 GB.
// =======================================================================
__global__ void __launch_bounds__(256)
presplit_kernel(const float* __restrict__ poly, half* __restrict__ Af) {
    const size_t base = ((size_t)blockIdx.x * 256 + threadIdx.x) * 16;
    if (base >= TOTE) return;
    const float4* src = (const float4*)(poly + base);
    uint32_t h[8];
#pragma unroll
    for (int j = 0; j < 4; j++) {
        float4 v = src[j];
        __half2 a = __floats2half2_rn(v.x * SCALE, v.y * SCALE);
        __half2 b = __floats2half2_rn(v.z * SCALE, v.w * SCALE);
        h[2 * j]     = *(const uint32_t*)&a;
        h[2 * j + 1] = *(const uint32_t*)&b;
    }
    uint4* d = (uint4*)(Af + base);
    d[0] = make_uint4(h[0], h[1], h[2], h[3]);
    d[1] = make_uint4(h[4], h[5], h[6], h[7]);
}

// =======================================================================
// poly MMA kernel: single-pass fp16. MTILE=256, 8 warps x 32 rows
// (2 row-frags), KCH=32, STG-stage cp.async pipeline.
// LDA=LDB=40 halves (80B stride: conflict-free ldmatrix, 16B aligned).
// =======================================================================
template <int C, int STG, int NCTA>
__global__ void __launch_bounds__(256, NCTA)
poly_mma_kernel(const half* __restrict__ Bg,
                const half* __restrict__ Ag,
                float* __restrict__ P) {
    constexpr int LDA = 40, LDB = 40;
    constexpr int APL = MTILE * LDA * 2;   // 20480
    constexpr int BPL = C * LDB * 2;       // 5120 / 2560
    constexpr int SS = APL + BPL;
    constexpr int NT = C / 16;
    extern __shared__ __align__(128) char smem[];
    const uint32_t sb = smem_u32(smem);

    const int tid = threadIdx.x;
    const int warp = tid >> 5;
    const int split = blockIdx.y;
    const int k = split >> 2;
    const int mbase = (split & 3) * KSPL;
    const int klen = min(NN - mbase, KSPL);
    const int nch = (klen + KCH - 1) / KCH;
    const int row0 = blockIdx.x * MTILE;

    // ---- B cp.async: plane C x 32 halves per chunk ----
    const int bc = tid >> 2, bk8 = (tid & 3) * 8;
    const half* bsrc = Bg + ((size_t)bc * KPOLY + k) * NN + mbase + bk8;
    const uint32_t bdoff = (uint32_t)(APL + (bc * LDB + bk8) * 2);
    auto issueB = [&](int ch) {
        if (C == 64 || tid < 128) {
            const int mc = ch * KCH;
            const int kv = klen - mc;
            const int pb = (bk8 < kv) ? 16 : 0;
            CP_ASYNC(sb + (ch % STG) * SS + bdoff, pb ? (bsrc + mc) : bsrc, pb);
        }
    };

    // ---- A cp.async: rows ar+64j (j=0..3), cols ak8..+7 ----
    const int ar = tid >> 2, ak8 = (tid & 3) * 8;
    const half* asrc[4];
    uint32_t adoff[4];
#pragma unroll
    for (int j = 0; j < 4; j++) {
        const int r = ar + j * 64;
        const int arow = min(row0 + r, NN - 1);  // clamp; rows discarded at store
        asrc[j] = Ag + ((size_t)k * NN + arow) * NN + mbase + ak8;
        adoff[j] = (uint32_t)((r * LDA + ak8) * 2);
    }
    auto issueA = [&](int ch) {
        const int mc = ch * KCH;
        const int kv = klen - mc;
        const int pb = (ak8 < kv) ? 16 : 0;
        const uint32_t base = sb + (ch % STG) * SS;
#pragma unroll
        for (int j = 0; j < 4; j++)
            CP_ASYNC(base + adoff[j], pb ? (asrc[j] + mc) : asrc[j], pb);
    };

    // ---- accumulators: 2 row-frags x NT ----
    wmma::fragment<wmma::accumulator, 16, 16, 16, float> acc[2][NT];
#pragma unroll
    for (int r = 0; r < 2; r++)
#pragma unroll
        for (int n = 0; n < NT; n++) wmma::fill_fragment(acc[r][n], 0.0f);

    auto domma = [&](int ch) {
        const half* Ap = (const half*)(smem + (ch % STG) * SS);
        const half* Bp = (const half*)(smem + (ch % STG) * SS + APL);
        const int wr = warp * 32;
#pragma unroll
        for (int ks = 0; ks < 2; ks++) {
            wmma::fragment<wmma::matrix_a, 16, 16, 16, half, wmma::row_major> fa[2];
#pragma unroll
            for (int r = 0; r < 2; r++)
                wmma::load_matrix_sync(fa[r], Ap + (wr + r * 16) * LDA + ks * 16, LDA);
#pragma unroll
            for (int n = 0; n < NT; n++) {
                wmma::fragment<wmma::matrix_b, 16, 16, 16, half, wmma::col_major> fb;
                wmma::load_matrix_sync(fb, Bp + n * 16 * LDB + ks * 16, LDB);
                wmma::mma_sync(acc[0][n], fa[0], fb, acc[0][n]);
                wmma::mma_sync(acc[1][n], fa[1], fb, acc[1][n]);
            }
        }
    };

    // ---- pipeline: STG stages, STG-1 groups in flight ----
#pragma unroll
    for (int i = 0; i < STG - 1; i++) { issueA(i); issueB(i); CP_COMMIT(); }
    for (int ch = 0; ch < nch; ch++) {
        if (STG == 4) CP_WAIT2(); else CP_WAIT1();
        __syncthreads();   // group(ch) visible; all warps past domma(ch-1)
        issueA(ch + STG - 1); issueB(ch + STG - 1); CP_COMMIT();
        domma(ch);
    }

    // ---- store partials (16-row frag granularity; NN-9984=16 => frag-exact) ----
#pragma unroll
    for (int r = 0; r < 2; r++) {
        const int nrow = row0 + warp * 32 + r * 16;
        if (nrow < NN) {
            float* o = P + ((size_t)split * NN + nrow) * C;
#pragma unroll
            for (int n = 0; n < NT; n++)
                wmma::store_matrix_sync(o + n * 16, acc[r][n], C, wmma::mem_row_major);
        }
    }
}

// =======================================================================
// reduce+relu: X1[n][d] = relu(sum_s P1[s][n][d]) / SCALE. Pure streaming.
// =======================================================================
__global__ void __launch_bounds__(256)
reduce_relu_kernel(float* __restrict__ X1) {
    int i = blockIdx.x * blockDim.x + threadIdx.x;
    if (i < NN * 64 / 4) {
        float4 acc = make_float4(0.f, 0.f, 0.f, 0.f);
#pragma unroll
        for (int s = 0; s < SPLITS; s++) {
            float4 v = *(const float4*)(g_P1 + (size_t)s * NN * 64 + (size_t)i * 4);
            acc.x += v.x; acc.y += v.y; acc.z += v.z; acc.w += v.w;
        }
        acc.x = fmaxf(acc.x, 0.f) * INV_SCALE;
        acc.y = fmaxf(acc.y, 0.f) * INV_SCALE;
        acc.z = fmaxf(acc.z, 0.f) * INV_SCALE;
        acc.w = fmaxf(acc.w, 0.f) * INV_SCALE;
        *(float4*)(X1 + (size_t)i * 4) = acc;
    }
}

// =======================================================================
// Small GEMM: Tt[c][k][n] = (X @ W[k])[n][c] as fp16. X is plain fp32 [n][64].
// =======================================================================
template <int DOUT>
__global__ void __launch_bounds__(256)
gemm_xw_kernel(const float* __restrict__ X, const float* __restrict__ W,
               half* __restrict__ T) {
    constexpr int DIN = 64;
    constexpr int MR = 256 / (DOUT / 8);
    __shared__ float Ws[DIN * DOUT];
    __shared__ float Xs[MR * (DIN + 1)];
    const int tid = threadIdx.x;
    const int kb = blockIdx.y;
    const int m0 = blockIdx.x * MR;

    for (int i = tid; i < DIN * DOUT; i += 256)
        Ws[i] = W[(size_t)kb * DIN * DOUT + i];
    for (int i = tid; i < MR * DIN; i += 256) {
        int r = i >> 6, d = i & 63;
        int n = m0 + r;
        if (n > NN - 1) n = NN - 1;
        Xs[r * (DIN + 1) + d] = X[(size_t)n * DIN + d];
    }
    __syncthreads();

    const int row = tid % MR;
    const int c0 = (tid / MR) * 8;
    float a[8];
#pragma unroll
    for (int c = 0; c < 8; c++) a[c] = 0.f;
#pragma unroll
    for (int d = 0; d < DIN; d++) {
        float xv = Xs[row * (DIN + 1) + d];
        float4 wa = *(const float4*)&Ws[d * DOUT + c0];
        float4 wb = *(const float4*)&Ws[d * DOUT + c0 + 4];
        a[0] = fmaf(xv, wa.x, a[0]); a[1] = fmaf(xv, wa.y, a[1]);
        a[2] = fmaf(xv, wa.z, a[2]); a[3] = fmaf(xv, wa.w, a[3]);
        a[4] = fmaf(xv, wb.x, a[4]); a[5] = fmaf(xv, wb.y, a[5]);
        a[6] = fmaf(xv, wb.z, a[6]); a[7] = fmaf(xv, wb.w, a[7]);
    }
    const int n = m0 + row;
    if (n < NN) {
#pragma unroll
        for (int c = 0; c < 8; c++)
            T[((size_t)(c0 + c) * KPOLY + kb) * NN + n] = __float2half_rn(a[c]);
    }
}

// Final reduction of layer-1 partials into d_out (descale P2's SCALE factor)
__global__ void reduce_out_kernel(float* __restrict__ out) {
    int i = blockIdx.x * blockDim.x + threadIdx.x;
    if (i < NN * 32 / 4) {
        float4 acc = make_float4(0.f, 0.f, 0.f, 0.f);
#pragma unroll
        for (int s = 0; s < SPLITS; s++) {
            float4 v = *(const float4*)(g_P2 + (size_t)s * NN * 32 + (size_t)i * 4);
            acc.x += v.x; acc.y += v.y; acc.z += v.z; acc.w += v.w;
        }
        acc.x *= INV_SCALE; acc.y *= INV_SCALE; acc.z *= INV_SCALE; acc.w *= INV_SCALE;
        *(float4*)(out + (size_t)i * 4) = acc;
    }
}

extern "C" void kernel_launch(void* const* d_in, const int* in_sizes, int n_in,
                              void* d_out, int out_size) {
    const float* x    = (const float*)d_in[0];
    const float* poly = (const float*)d_in[1];
    const float* W1   = (const float*)d_in[2];
    const float* W2   = (const float*)d_in[3];
    float* out = (float*)d_out;

    constexpr int SS64 = MTILE * 40 * 2 + 64 * 40 * 2;  // 25600
    constexpr int SS32 = MTILE * 40 * 2 + 32 * 40 * 2;  // 23040
    constexpr int SMEM64 = 4 * SS64;  // 102400 (4-stage, 2 CTAs/SM)
    constexpr int SMEM32 = 3 * SS32;  // 69120  (3-stage, 3 CTAs/SM)
    cudaFuncSetAttribute((const void*)poly_mma_kernel<64, 4, 2>,
                         cudaFuncAttributeMaxDynamicSharedMemorySize, SMEM64);
    cudaFuncSetAttribute((const void*)poly_mma_kernel<32, 3, 3>,
                         cudaFuncAttributeMaxDynamicSharedMemorySize, SMEM32);

    half *T1, *T2, *Af;
    float *P1, *P2, *X1;
    cudaGetSymbolAddress((void**)&T1, g_T1);
    cudaGetSymbolAddress((void**)&T2, g_T2);
    cudaGetSymbolAddress((void**)&Af, g_Af);
    cudaGetSymbolAddress((void**)&P1, g_P1);
    cudaGetSymbolAddress((void**)&P2, g_P2);
    cudaGetSymbolAddress((void**)&X1, g_X1);

    dim3 g1((NN + 31) / 32, KPOLY);
    dim3 g2((NN + 63) / 64, KPOLY);
    dim3 gp(MTG, SPLITS);
    const int psBlocks = (int)((TOTE / 16 + 255) / 256);

    presplit_kernel<<<psBlocks, 256>>>(poly, Af);                 // poly*S -> fp16
    gemm_xw_kernel<64><<<g1, 256>>>(x, W1, T1);                   // T1^T fp16
    poly_mma_kernel<64, 4, 2><<<gp, 256, SMEM64>>>(T1, Af, P1);   // P1 = S*poly @ T1
    reduce_relu_kernel<<<(NN * 64 / 4 + 255) / 256, 256>>>(X1);   // X1 = relu(sum P1)/S
    gemm_xw_kernel<32><<<g2, 256>>>(X1, W2, T2);                  // T2^T = X1 @ W2
    poly_mma_kernel<32, 3, 3><<<gp, 256, SMEM32>>>(T2, Af, P2);   // P2 = S*poly @ T2
    reduce_out_kernel<<<(NN * 32 / 4 + 255) / 256, 256>>>(out);   // out = sum P2 / S
}